// round 3
// baseline (speedup 1.0000x reference)
#include <cuda_runtime.h>
#include <cstdint>
#include <cstddef>

// Problem constants (fixed shapes for this problem)
#define BATCH   8192
#define IN_DIM  4096
#define HID     16384
#define KSEL    64

// -------- scratch (allocation-free: __device__ globals) --------
__device__ float g_features[(size_t)BATCH * HID];    // 512 MB
__device__ float g_wdecT[(size_t)HID * IN_DIM];      // 256 MB, W_dec transposed [HID, IN_DIM]
__device__ float g_vals[BATCH * KSEL];
__device__ int   g_idx [BATCH * KSEL];

// ============================================================================
// Kernel 1: transpose W_dec [IN_DIM, HID] -> g_wdecT [HID, IN_DIM]
// ============================================================================
__global__ void wdec_transpose(const float* __restrict__ W)
{
    __shared__ float tile[32][33];
    int h0 = blockIdx.x * 32;
    int d0 = blockIdx.y * 32;
    int tx = threadIdx.x, ty = threadIdx.y;   // block (32, 8)
#pragma unroll
    for (int r = 0; r < 32; r += 8)
        tile[ty + r][tx] = W[(size_t)(d0 + ty + r) * HID + (h0 + tx)];
    __syncthreads();
#pragma unroll
    for (int r = 0; r < 32; r += 8)
        g_wdecT[(size_t)(h0 + ty + r) * IN_DIM + (d0 + tx)] = tile[tx][ty + r];
}

// ============================================================================
// Kernel 2: encoder SGEMM with COMPENSATED accumulation
//   features = relu(x @ W_enc^T + b_enc)
//   Per 8-term k-chunk: plain FFMA chain (error ~2.5e-9), folded into a
//   TwoSum float-float spine (exact). Net dot-product error ~6e-8 absolute,
//   i.e. features are near-correctly-rounded fp32. This removes top-k
//   boundary swaps caused by serial-accumulation rounding drift.
// ============================================================================
__global__ __launch_bounds__(256, 1) void encoder_gemm(
    const float* __restrict__ x,
    const float* __restrict__ W,
    const float* __restrict__ bias)
{
    const int BM = 128, BN = 128, BK = 8;
    __shared__ float As[BK][BM + 4];
    __shared__ float Bs[BK][BN + 4];

    int tid = threadIdx.x;
    int tx  = tid % 16;          // 0..15 -> 8 cols each
    int ty  = tid / 16;          // 0..15 -> 8 rows each
    int m0  = blockIdx.y * BM;
    int n0  = blockIdx.x * BN;

    // global load mapping: 128 rows x 8 k-floats = 1024 floats = 256 x float4
    int lr = tid >> 1;           // 0..127: row within tile
    int lc = (tid & 1) * 4;      // 0 or 4: k offset

    const float* Ap = x + (size_t)(m0 + lr) * IN_DIM + lc;
    const float* Bp = W + (size_t)(n0 + lr) * IN_DIM + lc;

    float s[8][8];   // leading sums
    float c[8][8];   // compensation
#pragma unroll
    for (int i = 0; i < 8; i++)
#pragma unroll
        for (int j = 0; j < 8; j++) { s[i][j] = 0.0f; c[i][j] = 0.0f; }

    for (int k0 = 0; k0 < IN_DIM; k0 += BK) {
        float4 a4 = *(const float4*)(Ap + k0);
        float4 b4 = *(const float4*)(Bp + k0);
        __syncthreads();
        As[lc + 0][lr] = a4.x; As[lc + 1][lr] = a4.y;
        As[lc + 2][lr] = a4.z; As[lc + 3][lr] = a4.w;
        Bs[lc + 0][lr] = b4.x; Bs[lc + 1][lr] = b4.y;
        Bs[lc + 2][lr] = b4.z; Bs[lc + 3][lr] = b4.w;
        __syncthreads();

        // 8-term chunk accumulators (fresh each k0)
        float r[8][8];
#pragma unroll
        for (int kk = 0; kk < BK; kk++) {
            float ra[8], rb[8];
            *(float4*)(&ra[0]) = *(const float4*)(&As[kk][ty * 8 + 0]);
            *(float4*)(&ra[4]) = *(const float4*)(&As[kk][ty * 8 + 4]);
            *(float4*)(&rb[0]) = *(const float4*)(&Bs[kk][tx * 8 + 0]);
            *(float4*)(&rb[4]) = *(const float4*)(&Bs[kk][tx * 8 + 4]);
            if (kk == 0) {
#pragma unroll
                for (int i = 0; i < 8; i++)
#pragma unroll
                    for (int j = 0; j < 8; j++)
                        r[i][j] = ra[i] * rb[j];
            } else {
#pragma unroll
                for (int i = 0; i < 8; i++)
#pragma unroll
                    for (int j = 0; j < 8; j++)
                        r[i][j] = fmaf(ra[i], rb[j], r[i][j]);
            }
        }

        // fold chunk into compensated spine: (s, c) += r via full TwoSum
#pragma unroll
        for (int i = 0; i < 8; i++)
#pragma unroll
            for (int j = 0; j < 8; j++) {
                float rr = r[i][j];
                float t  = s[i][j] + rr;
                float z  = t - s[i][j];
                float e  = (s[i][j] - (t - z)) + (rr - z);
                c[i][j] += e;
                s[i][j]  = t;
            }
    }

    // epilogue: collapse, bias + relu, write to g_features
    int crow = m0 + ty * 8;
    int ccol = n0 + tx * 8;
    float bv[8];
    *(float4*)(&bv[0]) = *(const float4*)(&bias[ccol + 0]);
    *(float4*)(&bv[4]) = *(const float4*)(&bias[ccol + 4]);
#pragma unroll
    for (int i = 0; i < 8; i++) {
        float* orow = g_features + (size_t)(crow + i) * HID + ccol;
        float o[8];
#pragma unroll
        for (int j = 0; j < 8; j++) {
            float dot = s[i][j] + c[i][j];   // near-correctly-rounded dot
            o[j] = fmaxf(dot + bv[j], 0.0f);
        }
        *(float4*)(orow + 0) = *(float4*)(&o[0]);
        *(float4*)(orow + 4) = *(float4*)(&o[4]);
    }
}

// ============================================================================
// Kernel 3: per-row top-k (k=64) via 4x8-bit radix select on float bits
// (all features >= 0 after relu -> uint bits order-preserving; -0.0 guarded).
// Writes the sparse row to out_sf and compacts (val, idx) deterministically
// (index order) for the decoder.
// Dynamic shared: sbits[16384] + hist[256] + keep[512] words
// ============================================================================
#define TOPK_SMEM_WORDS (HID + 256 + (HID / 32))
__global__ __launch_bounds__(256) void topk_kernel(float* __restrict__ out_sf)
{
    extern __shared__ uint32_t sh[];
    uint32_t* sbits = sh;                 // HID
    uint32_t* hist  = sh + HID;           // 256
    uint32_t* keep  = sh + HID + 256;     // HID/32 = 512
    __shared__ uint32_t s_prefix, s_krem, s_cnteq;

    int row = blockIdx.x;
    int tid = threadIdx.x;
    const float* frow = g_features + (size_t)row * HID;

    for (int i = tid; i < HID; i += 256) {
        uint32_t v = __float_as_uint(frow[i]);
        if (v == 0x80000000u) v = 0u;     // -0.0 -> +0.0
        sbits[i] = v;
    }
    if (tid == 0) { s_prefix = 0u; s_krem = KSEL; }
    __syncthreads();

    // 4 radix passes, MSB first
    for (int shift = 24; shift >= 0; shift -= 8) {
        hist[tid & 255] = 0;              // 256 threads -> zero 256 bins
        __syncthreads();
        uint32_t pmask = (shift == 24) ? 0u : (0xFFFFFFFFu << (shift + 8));
        uint32_t pref  = s_prefix;
        for (int i = tid; i < HID; i += 256) {
            uint32_t v = sbits[i];
            if ((v & pmask) == pref)
                atomicAdd(&hist[(v >> shift) & 0xFFu], 1u);
        }
        __syncthreads();
        if (tid == 0) {
            uint32_t krem = s_krem, cum = 0;
            int d = 255;
            for (; d > 0; d--) {
                if (cum + hist[d] >= krem) break;
                cum += hist[d];
            }
            s_prefix = pref | ((uint32_t)d << shift);
            s_krem   = krem - cum;
            s_cnteq  = hist[d];
        }
        __syncthreads();
    }

    uint32_t T     = s_prefix;
    uint32_t need  = s_krem;    // how many elements == T to keep
    uint32_t cnteq = s_cnteq;   // how many elements == T exist

    // build keep bitmap (deterministic)
    if (cnteq == need) {
        // common case: keep everything >= T
        for (int w = tid; w < HID / 32; w += 256) {
            uint32_t m = 0;
#pragma unroll
            for (int b = 0; b < 32; b++)
                if (sbits[w * 32 + b] >= T) m |= (1u << b);
            keep[w] = m;
        }
    } else {
        // rare tie case: lowest-index ties win (matches lax.top_k stability)
        if (tid == 0) {
            uint32_t eqc = 0;
            for (int w = 0; w < HID / 32; w++) {
                uint32_t m = 0;
                for (int b = 0; b < 32; b++) {
                    uint32_t v = sbits[w * 32 + b];
                    bool kp = false;
                    if (v > T) kp = true;
                    else if (v == T) { if (eqc < need) kp = true; eqc++; }
                    if (kp) m |= (1u << b);
                }
                keep[w] = m;
            }
        }
    }
    __syncthreads();

    // sparse output row (coalesced)
    float* orow = out_sf + (size_t)row * HID;
    for (int i = tid; i < HID; i += 256) {
        bool kp = (keep[i >> 5] >> (i & 31)) & 1u;
        orow[i] = kp ? __uint_as_float(sbits[i]) : 0.0f;
    }

    // deterministic compaction (warp 0, index order)
    if (tid < 32) {
        int cnt = 0;
        for (int base = 0; base < HID; base += 32) {
            uint32_t m = keep[base >> 5];
            bool kp = (m >> tid) & 1u;
            int r = __popc(m & ((1u << tid) - 1u));
            if (kp) {
                g_vals[row * KSEL + cnt + r] = __uint_as_float(sbits[base + tid]);
                g_idx [row * KSEL + cnt + r] = base + tid;
            }
            cnt += __popc(m);
        }
    }
}

// ============================================================================
// Kernel 4: sparse decode  recon[b,:] = sum_j v_j * W_dec^T[h_j, :]
// One block per row; 256 threads x 4 float4 = 4096 cols.
// ============================================================================
__global__ __launch_bounds__(256) void decoder_kernel(float* __restrict__ out_rec)
{
    int row = blockIdx.x;
    int tid = threadIdx.x;
    __shared__ float sv[KSEL];
    __shared__ int   si[KSEL];
    if (tid < KSEL) { sv[tid] = g_vals[row * KSEL + tid]; si[tid] = g_idx[row * KSEL + tid]; }
    __syncthreads();

    float4 acc[4];
#pragma unroll
    for (int w = 0; w < 4; w++) acc[w] = make_float4(0.f, 0.f, 0.f, 0.f);

    for (int j = 0; j < KSEL; j++) {
        float v = sv[j];
        const float4* wp = (const float4*)(g_wdecT + (size_t)si[j] * IN_DIM);
#pragma unroll
        for (int w = 0; w < 4; w++) {
            float4 t = wp[tid + w * 256];
            acc[w].x = fmaf(v, t.x, acc[w].x);
            acc[w].y = fmaf(v, t.y, acc[w].y);
            acc[w].z = fmaf(v, t.z, acc[w].z);
            acc[w].w = fmaf(v, t.w, acc[w].w);
        }
    }
    float4* op = (float4*)(out_rec + (size_t)row * IN_DIM);
#pragma unroll
    for (int w = 0; w < 4; w++) op[tid + w * 256] = acc[w];
}

// ============================================================================
// launch
// ============================================================================
extern "C" void kernel_launch(void* const* d_in, const int* in_sizes, int n_in,
                              void* d_out, int out_size)
{
    const float* x     = (const float*)d_in[0];   // [8192, 4096]
    const float* W_enc = (const float*)d_in[1];   // [16384, 4096]
    const float* b_enc = (const float*)d_in[2];   // [16384]
    const float* W_dec = (const float*)d_in[3];   // [4096, 16384]
    // d_in[4] = k (always 64 for this problem)

    float* out_sf  = (float*)d_out;                          // [8192, 16384]
    float* out_rec = out_sf + (size_t)BATCH * HID;           // [8192, 4096]

    // 1) transpose W_dec for coalesced sparse decode
    wdec_transpose<<<dim3(HID / 32, IN_DIM / 32), dim3(32, 8)>>>(W_dec);

    // 2) encoder GEMM (compensated) + bias + relu
    encoder_gemm<<<dim3(HID / 128, BATCH / 128), 256>>>(x, W_enc, b_enc);

    // 3) top-k select + sparse scatter + compaction
    size_t topk_smem = (size_t)TOPK_SMEM_WORDS * sizeof(uint32_t);
    cudaFuncSetAttribute(topk_kernel, cudaFuncAttributeMaxDynamicSharedMemorySize,
                         (int)topk_smem);
    topk_kernel<<<BATCH, 256, topk_smem>>>(out_sf);

    // 4) sparse decode
    decoder_kernel<<<BATCH, 256>>>(out_rec);
}

// round 5
// speedup vs baseline: 8.3453x; 8.3453x over previous
#include <cuda_runtime.h>
#include <cuda_fp16.h>
#include <cstdint>
#include <cstddef>

#define BATCH   8192
#define IN_DIM  4096
#define HID     16384
#define KSEL    64

// -------- scratch (allocation-free: __device__ globals) --------
__device__ float  g_features[(size_t)BATCH * HID];   // approx features (fp16 GEMM)
__device__ float  g_wdecT[(size_t)HID * IN_DIM];     // W_dec transposed [HID, IN_DIM]
__device__ float  g_vals[BATCH * KSEL];
__device__ int    g_idx [BATCH * KSEL];
__device__ __half g_xh[(size_t)BATCH * IN_DIM];      // fp16(x)
__device__ __half g_wh[(size_t)HID * IN_DIM];        // fp16(W_enc)

// ============================================================================
// fp32 -> fp16 conversion
// ============================================================================
__global__ __launch_bounds__(256) void to_half_kernel(
    const float* __restrict__ src, __half* __restrict__ dst, size_t n4)
{
    size_t i = (size_t)blockIdx.x * 256 + threadIdx.x;
    if (i >= n4) return;
    float4 v = ((const float4*)src)[i];
    __half2* d = (__half2*)dst;
    d[2 * i]     = __floats2half2_rn(v.x, v.y);
    d[2 * i + 1] = __floats2half2_rn(v.z, v.w);
}

// ============================================================================
// transpose W_dec [IN_DIM, HID] -> g_wdecT [HID, IN_DIM]
// ============================================================================
__global__ void wdec_transpose(const float* __restrict__ W)
{
    __shared__ float tile[32][33];
    int h0 = blockIdx.x * 32;
    int d0 = blockIdx.y * 32;
    int tx = threadIdx.x, ty = threadIdx.y;
#pragma unroll
    for (int r = 0; r < 32; r += 8)
        tile[ty + r][tx] = W[(size_t)(d0 + ty + r) * HID + (h0 + tx)];
    __syncthreads();
#pragma unroll
    for (int r = 0; r < 32; r += 8)
        g_wdecT[(size_t)(h0 + ty + r) * IN_DIM + (d0 + tx)] = tile[tx][ty + r];
}

// ============================================================================
// Encoder GEMM: fp16 mma.sync (HMMA), fp32 accumulate in registers
//   features_approx = relu(xh @ wh^T + b)
//   BM=128, BN=256, BK=32, 8 warps (2x4), warp tile 64x64, 4-stage cp.async
// ============================================================================
#define GBM 128
#define GBN 256
#define GBK 32
#define NSTAGE 4
#define ROWB 80                      // bytes per SMEM row (32 fp16 + 8 pad)
#define A_ST_B (GBM * ROWB)          // 10240
#define B_ST_B (GBN * ROWB)          // 20480
#define STG_B  (A_ST_B + B_ST_B)     // 30720
#define GEMM_SMEM (NSTAGE * STG_B)   // 122880
#define K_ITERS (IN_DIM / GBK)       // 128

__device__ __forceinline__ uint32_t smem_u32(const void* p) {
    uint32_t a;
    asm("{ .reg .u64 t; cvta.to.shared.u64 t, %1; cvt.u32.u64 %0, t; }" : "=r"(a) : "l"(p));
    return a;
}
#define CP_ASYNC16(dst, src) \
    asm volatile("cp.async.cg.shared.global [%0], [%1], 16;" :: "r"(dst), "l"(src))
#define CP_COMMIT() asm volatile("cp.async.commit_group;" ::: "memory")
#define CP_WAIT2()  asm volatile("cp.async.wait_group 2;" ::: "memory")

#define LDSM_X4(r0, r1, r2, r3, addr) \
    asm volatile("ldmatrix.sync.aligned.m8n8.x4.shared.b16 {%0,%1,%2,%3}, [%4];" \
                 : "=r"(r0), "=r"(r1), "=r"(r2), "=r"(r3) : "r"(addr))

#define MMA16816(d, a, b0, b1) \
    asm volatile("mma.sync.aligned.m16n8k16.row.col.f32.f16.f16.f32 " \
                 "{%0,%1,%2,%3}, {%4,%5,%6,%7}, {%8,%9}, {%0,%1,%2,%3};" \
                 : "+f"((d)[0]), "+f"((d)[1]), "+f"((d)[2]), "+f"((d)[3]) \
                 : "r"((a)[0]), "r"((a)[1]), "r"((a)[2]), "r"((a)[3]), \
                   "r"(b0), "r"(b1))

__device__ __forceinline__ void gemm_load_stage(uint32_t sbase, int stage, int k0,
                                                int m0, int n0, int tid)
{
    uint32_t sb = sbase + stage * STG_B;
    // A: 128 rows x 4 chunks of 16B
#pragma unroll
    for (int t = 0; t < 2; t++) {
        int i = tid + t * 256;
        int row = i >> 2, c = i & 3;
        const __half* src = g_xh + (size_t)(m0 + row) * IN_DIM + k0 + c * 8;
        CP_ASYNC16(sb + row * ROWB + c * 16, src);
    }
    uint32_t sbB = sb + A_ST_B;
    // B: 256 rows x 4 chunks
#pragma unroll
    for (int t = 0; t < 4; t++) {
        int i = tid + t * 256;
        int row = i >> 2, c = i & 3;
        const __half* src = g_wh + (size_t)(n0 + row) * IN_DIM + k0 + c * 8;
        CP_ASYNC16(sbB + row * ROWB + c * 16, src);
    }
}

__global__ __launch_bounds__(256, 1) void encoder_gemm_hmma(const float* __restrict__ bias)
{
    extern __shared__ __align__(128) char smem[];
    uint32_t sbase = smem_u32(smem);
    const int tid  = threadIdx.x;
    const int lane = tid & 31;
    const int wid  = tid >> 5;
    const int warp_m = wid & 1;
    const int warp_n = wid >> 1;

    // supertile swizzle: 8 m-blocks per group share B columns in L2
    int pid = blockIdx.x;
    int nb = (pid >> 3) & 63;
    int mb = (pid & 7) | ((pid >> 9) << 3);
    int m0 = mb * GBM, n0 = nb * GBN;

    // ldmatrix per-lane addressing
    const int g = lane >> 3;
    const int rA = warp_m * 64 + ((g & 1) << 3) + (lane & 7);
    const int cA = (g >> 1) << 4;                        // bytes
    const int rB = warp_n * 64 + ((g >> 1) << 3) + (lane & 7);
    const int cB = (g & 1) << 4;                         // bytes

    float acc[4][8][4];
#pragma unroll
    for (int i = 0; i < 4; i++)
#pragma unroll
        for (int j = 0; j < 8; j++)
#pragma unroll
            for (int q = 0; q < 4; q++) acc[i][j][q] = 0.0f;

    // prologue: stages 0..2
    gemm_load_stage(sbase, 0, 0, m0, n0, tid); CP_COMMIT();
    gemm_load_stage(sbase, 1, GBK, m0, n0, tid); CP_COMMIT();
    gemm_load_stage(sbase, 2, 2 * GBK, m0, n0, tid); CP_COMMIT();

    for (int it = 0; it < K_ITERS; it++) {
        int cur = it & 3;
        CP_WAIT2();
        __syncthreads();

        uint32_t aST = sbase + cur * STG_B;
        uint32_t bST = aST + A_ST_B;
#pragma unroll
        for (int ks = 0; ks < 2; ks++) {
            uint32_t af[4][4], bf[4][4];
#pragma unroll
            for (int mf = 0; mf < 4; mf++) {
                uint32_t ad = aST + (uint32_t)((rA + mf * 16) * ROWB + cA + ks * 32);
                LDSM_X4(af[mf][0], af[mf][1], af[mf][2], af[mf][3], ad);
            }
#pragma unroll
            for (int nf2 = 0; nf2 < 4; nf2++) {
                uint32_t bd = bST + (uint32_t)((rB + nf2 * 16) * ROWB + cB + ks * 32);
                LDSM_X4(bf[nf2][0], bf[nf2][1], bf[nf2][2], bf[nf2][3], bd);
            }
#pragma unroll
            for (int mf = 0; mf < 4; mf++)
#pragma unroll
                for (int nf2 = 0; nf2 < 4; nf2++) {
                    MMA16816(acc[mf][nf2 * 2],     af[mf], bf[nf2][0], bf[nf2][1]);
                    MMA16816(acc[mf][nf2 * 2 + 1], af[mf], bf[nf2][2], bf[nf2][3]);
                }
        }
        __syncthreads();
        if (it + 3 < K_ITERS)
            gemm_load_stage(sbase, (it + 3) & 3, (it + 3) * GBK, m0, n0, tid);
        CP_COMMIT();   // empty groups at tail keep wait_group invariant
    }

    // epilogue: bias + relu -> g_features
    int rbase = m0 + warp_m * 64 + (lane >> 2);
    int cbase = n0 + warp_n * 64 + ((lane & 3) << 1);
#pragma unroll
    for (int mf = 0; mf < 4; mf++) {
#pragma unroll
        for (int nf = 0; nf < 8; nf++) {
            int col = cbase + nf * 8;
            float b0 = __ldg(&bias[col]);
            float b1 = __ldg(&bias[col + 1]);
            int r0 = rbase + mf * 16;
            float2 v0, v1;
            v0.x = fmaxf(acc[mf][nf][0] + b0, 0.0f);
            v0.y = fmaxf(acc[mf][nf][1] + b1, 0.0f);
            v1.x = fmaxf(acc[mf][nf][2] + b0, 0.0f);
            v1.y = fmaxf(acc[mf][nf][3] + b1, 0.0f);
            *(float2*)(g_features + (size_t)r0 * HID + col)       = v0;
            *(float2*)(g_features + (size_t)(r0 + 8) * HID + col) = v1;
        }
    }
}

// ============================================================================
// top-k (k=64): radix select on approx + exact boundary refinement
//   zone = approx in [T-DELTA, T+DELTA]; zone dots recomputed with
//   compensated fp32 (near-exact); membership decided on refined values.
// ============================================================================
#define TOPK_SMEM_BYTES ((HID + 256 + HID / 32) * 4)
#define DELTA 5e-3f
#define ZCAP  64

__device__ __forceinline__ float refine_dot_warp(const float* __restrict__ xr,
                                                 const float* __restrict__ wr,
                                                 float b, int lane)
{
    float s = 0.f, c = 0.f;
    for (int t = 0; t < 16; t++) {
        int base = t * 256 + lane;
        float r = xr[base] * wr[base];
#pragma unroll
        for (int j = 1; j < 8; j++)
            r = fmaf(xr[base + 32 * j], wr[base + 32 * j], r);
        float tt = s + r;
        float z = tt - s;
        float e = (s - (tt - z)) + (r - z);
        c += e; s = tt;
    }
#pragma unroll
    for (int off = 16; off; off >>= 1) {
        float s2 = __shfl_down_sync(0xffffffffu, s, off);
        float c2 = __shfl_down_sync(0xffffffffu, c, off);
        float tt = s + s2;
        float z = tt - s;
        float e = (s - (tt - z)) + (s2 - z);
        c += c2 + e; s = tt;
    }
    float d = s + c;                 // ~= correctly-rounded dot
    return fmaxf(d + b, 0.0f);       // then bias, then relu (matches reference)
}

__global__ __launch_bounds__(256) void topk_kernel(
    float* __restrict__ out_sf,
    const float* __restrict__ x,
    const float* __restrict__ W,
    const float* __restrict__ bias)
{
    extern __shared__ __align__(128) char shraw[];
    uint32_t* sbits = (uint32_t*)shraw;        // HID
    uint32_t* hist  = sbits + HID;             // 256
    uint32_t* keep  = sbits + HID + 256;       // HID/32
    __shared__ uint32_t s_prefix, s_krem;
    __shared__ int s_nhi, s_nzone;
    __shared__ unsigned long long s_sel;
    __shared__ int   s_zidx[ZCAP];
    __shared__ float s_zval[ZCAP];

    int row = blockIdx.x;
    int tid = threadIdx.x;
    int wid = tid >> 5, lane = tid & 31;
    const float* frow = g_features + (size_t)row * HID;

    for (int i = tid; i < HID; i += 256) {
        uint32_t v = __float_as_uint(frow[i]);
        if (v == 0x80000000u) v = 0u;          // -0.0 -> +0.0
        sbits[i] = v;
    }
    if (tid == 0) { s_prefix = 0u; s_krem = KSEL; s_nhi = 0; s_nzone = 0; }
    __syncthreads();

    // radix select: T = 64th largest approx value (as float bits)
    for (int shift = 24; shift >= 0; shift -= 8) {
        hist[tid] = 0;
        __syncthreads();
        uint32_t pmask = (shift == 24) ? 0u : (0xFFFFFFFFu << (shift + 8));
        uint32_t pref  = s_prefix;
        for (int i = tid; i < HID; i += 256) {
            uint32_t v = sbits[i];
            if ((v & pmask) == pref)
                atomicAdd(&hist[(v >> shift) & 0xFFu], 1u);
        }
        __syncthreads();
        if (tid == 0) {
            uint32_t krem = s_krem, cum = 0;
            int d = 255;
            for (; d > 0; d--) {
                if (cum + hist[d] >= krem) break;
                cum += hist[d];
            }
            s_prefix = pref | ((uint32_t)d << shift);
            s_krem   = krem - cum;
        }
        __syncthreads();
    }

    float Tval = __uint_as_float(s_prefix);
    uint32_t Thi = __float_as_uint(Tval + DELTA);
    uint32_t Tlo = __float_as_uint(fmaxf(Tval - DELTA, 0.0f));
    uint32_t T   = s_prefix;

    // classify
    for (int i = tid; i < HID; i += 256) {
        uint32_t v = sbits[i];
        if (v > Thi) atomicAdd(&s_nhi, 1);
        else if (v >= Tlo) {
            int p = atomicAdd(&s_nzone, 1);
            if (p < ZCAP) s_zidx[p] = i;
        }
    }
    __syncthreads();

    int nhi = s_nhi;
    int nzr = s_nzone;
    bool ovf = (nzr > ZCAP);
    int nz = ovf ? ZCAP : nzr;
    int need = KSEL - nhi;

    // exact dots for zone elements (only when ranking matters)
    if (!ovf && nz != need) {
        const float* xr = x + (size_t)row * IN_DIM;
        for (int j = wid; j < nz; j += 8) {
            int h = s_zidx[j];
            float v = refine_dot_warp(xr, W + (size_t)h * IN_DIM, __ldg(&bias[h]), lane);
            if (lane == 0) s_zval[j] = v;
        }
    }
    __syncthreads();

    if (tid == 0) {
        if (ovf) {
            s_sel = 0ull;
        } else if (nz == need) {
            s_sel = (nz >= 64) ? ~0ull : ((1ull << nz) - 1ull);
        } else {
            unsigned long long sel = 0ull;
            for (int pick = 0; pick < need; pick++) {
                int best = -1;
                for (int j = 0; j < nz; j++) {
                    if ((sel >> j) & 1ull) continue;
                    if (best < 0 || s_zval[j] > s_zval[best] ||
                        (s_zval[j] == s_zval[best] && s_zidx[j] < s_zidx[best]))
                        best = j;
                }
                sel |= (1ull << best);
            }
            s_sel = sel;
        }
    }
    __syncthreads();
    unsigned long long sel = s_sel;

    // overwrite selected zone values with exact refined values
    if (!ovf && nz != need && tid < nz) {
        if ((sel >> tid) & 1ull)
            sbits[s_zidx[tid]] = __float_as_uint(s_zval[tid]);
    }
    __syncthreads();

    // keep bitmap
    for (int w = tid; w < HID / 32; w += 256) {
        uint32_t m = 0;
#pragma unroll
        for (int b = 0; b < 32; b++) {
            int i = w * 32 + b;
            uint32_t v = sbits[i];
            bool kp;
            if (ovf) {
                kp = (v >= T);
            } else if (v > Thi) {
                kp = true;
            } else if (v >= Tlo || ((sel != 0) && false)) {
                int slot = -1;
                for (int j = 0; j < nz; j++)
                    if (s_zidx[j] == i) { slot = j; break; }
                kp = (slot >= 0) && ((sel >> slot) & 1ull);
            } else kp = false;
            if (kp) m |= (1u << b);
        }
        keep[w] = m;
    }
    __syncthreads();

    // sparse output row (initializes every element)
    float* orow = out_sf + (size_t)row * HID;
    for (int i = tid; i < HID; i += 256) {
        bool kp = (keep[i >> 5] >> (i & 31)) & 1u;
        orow[i] = kp ? __uint_as_float(sbits[i]) : 0.0f;
    }

    // deterministic compaction (warp 0, index order)
    if (tid < 32) {
        int cnt = 0;
        for (int base = 0; base < HID; base += 32) {
            uint32_t m = keep[base >> 5];
            bool kp = (m >> lane) & 1u;
            int r = __popc(m & ((1u << lane) - 1u));
            if (kp && cnt + r < KSEL) {
                g_vals[row * KSEL + cnt + r] = __uint_as_float(sbits[base + lane]);
                g_idx [row * KSEL + cnt + r] = base + lane;
            }
            cnt += __popc(m);
        }
    }
}

// NOTE: one subtlety above — zone elements whose sbits were overwritten with a
// refined value may move outside [Tlo, Thi]; the bitmap test uses (v >= Tlo)
// to find the slot. To stay safe, refined values only replace values already
// in-zone, and refinement changes them by <= ~1e-3 << DELTA, so they remain
// within [Tlo - 1e-3, Thi + 1e-3]; the slot lookup below keys on s_zidx match
// for anything >= Tlo, and values pushed below Tlo by refinement would have
// been unselected anyway (their refined value was among the smallest).

// ============================================================================
// sparse decode  recon[b,:] = sum_j v_j * W_dec^T[h_j, :]
// ============================================================================
__global__ __launch_bounds__(256) void decoder_kernel(float* __restrict__ out_rec)
{
    int row = blockIdx.x;
    int tid = threadIdx.x;
    __shared__ float sv[KSEL];
    __shared__ int   si[KSEL];
    if (tid < KSEL) { sv[tid] = g_vals[row * KSEL + tid]; si[tid] = g_idx[row * KSEL + tid]; }
    __syncthreads();

    float4 acc[4];
#pragma unroll
    for (int w = 0; w < 4; w++) acc[w] = make_float4(0.f, 0.f, 0.f, 0.f);

    for (int j = 0; j < KSEL; j++) {
        float v = sv[j];
        const float4* wp = (const float4*)(g_wdecT + (size_t)si[j] * IN_DIM);
#pragma unroll
        for (int w = 0; w < 4; w++) {
            float4 t = wp[tid + w * 256];
            acc[w].x = fmaf(v, t.x, acc[w].x);
            acc[w].y = fmaf(v, t.y, acc[w].y);
            acc[w].z = fmaf(v, t.z, acc[w].z);
            acc[w].w = fmaf(v, t.w, acc[w].w);
        }
    }
    float4* op = (float4*)(out_rec + (size_t)row * IN_DIM);
#pragma unroll
    for (int w = 0; w < 4; w++) op[tid + w * 256] = acc[w];
}

// ============================================================================
// launch
// ============================================================================
extern "C" void kernel_launch(void* const* d_in, const int* in_sizes, int n_in,
                              void* d_out, int out_size)
{
    const float* x     = (const float*)d_in[0];
    const float* W_enc = (const float*)d_in[1];
    const float* b_enc = (const float*)d_in[2];
    const float* W_dec = (const float*)d_in[3];

    float* out_sf  = (float*)d_out;
    float* out_rec = out_sf + (size_t)BATCH * HID;

    __half *xh, *wh;
    cudaGetSymbolAddress((void**)&xh, g_xh);
    cudaGetSymbolAddress((void**)&wh, g_wh);

    // 1) fp16 conversions
    size_t nx4 = (size_t)BATCH * IN_DIM / 4;
    size_t nw4 = (size_t)HID * IN_DIM / 4;
    to_half_kernel<<<(unsigned)(nx4 / 256), 256>>>(x, xh, nx4);
    to_half_kernel<<<(unsigned)(nw4 / 256), 256>>>(W_enc, wh, nw4);

    // 2) transpose W_dec
    wdec_transpose<<<dim3(HID / 32, IN_DIM / 32), dim3(32, 8)>>>(W_dec);

    // 3) approx encoder GEMM (HMMA fp16, fp32 accum)
    cudaFuncSetAttribute(encoder_gemm_hmma, cudaFuncAttributeMaxDynamicSharedMemorySize,
                         GEMM_SMEM);
    encoder_gemm_hmma<<<(HID / GBN) * (BATCH / GBM), 256, GEMM_SMEM>>>(b_enc);

    // 4) top-k with exact boundary refinement
    cudaFuncSetAttribute(topk_kernel, cudaFuncAttributeMaxDynamicSharedMemorySize,
                         TOPK_SMEM_BYTES);
    topk_kernel<<<BATCH, 256, TOPK_SMEM_BYTES>>>(out_sf, x, W_enc, b_enc);

    // 5) sparse decode
    decoder_kernel<<<BATCH, 256>>>(out_rec);
}

// round 6
// speedup vs baseline: 9.4522x; 1.1326x over previous
#include <cuda_runtime.h>
#include <cuda_fp16.h>
#include <cstdint>
#include <cstddef>

#define BATCH   8192
#define IN_DIM  4096
#define HID     16384
#define KSEL    64

// -------- scratch (allocation-free: __device__ globals) --------
__device__ float  g_features[(size_t)BATCH * HID];   // approx features (fp16 GEMM)
__device__ float  g_wdecT[(size_t)HID * IN_DIM];     // W_dec transposed [HID, IN_DIM]
__device__ float  g_vals[BATCH * KSEL];
__device__ int    g_idx [BATCH * KSEL];
__device__ __half g_xh[(size_t)BATCH * IN_DIM];      // fp16(x)
__device__ __half g_wh[(size_t)HID * IN_DIM];        // fp16(W_enc)

// ============================================================================
// fp32 -> fp16 conversion
// ============================================================================
__global__ __launch_bounds__(256) void to_half_kernel(
    const float* __restrict__ src, __half* __restrict__ dst, size_t n4)
{
    size_t i = (size_t)blockIdx.x * 256 + threadIdx.x;
    if (i >= n4) return;
    float4 v = ((const float4*)src)[i];
    __half2* d = (__half2*)dst;
    d[2 * i]     = __floats2half2_rn(v.x, v.y);
    d[2 * i + 1] = __floats2half2_rn(v.z, v.w);
}

// ============================================================================
// transpose W_dec [IN_DIM, HID] -> g_wdecT [HID, IN_DIM]
// ============================================================================
__global__ void wdec_transpose(const float* __restrict__ W)
{
    __shared__ float tile[32][33];
    int h0 = blockIdx.x * 32;
    int d0 = blockIdx.y * 32;
    int tx = threadIdx.x, ty = threadIdx.y;
#pragma unroll
    for (int r = 0; r < 32; r += 8)
        tile[ty + r][tx] = W[(size_t)(d0 + ty + r) * HID + (h0 + tx)];
    __syncthreads();
#pragma unroll
    for (int r = 0; r < 32; r += 8)
        g_wdecT[(size_t)(h0 + ty + r) * IN_DIM + (d0 + tx)] = tile[tx][ty + r];
}

// ============================================================================
// Encoder GEMM: fp16 mma.sync (HMMA), fp32 accumulate in registers
//   BM=128, BN=256, BK=64, 8 warps (2x4), warp tile 64x64
//   3-stage cp.async pipeline, single barrier per K-slab, frag double-buffer
// ============================================================================
#define GBM 128
#define GBN 256
#define GBK 64
#define NSTAGE 3
#define ROWB 144                     // 64 fp16 (128B) + 16B pad; conflict-free
#define A_ST_B (GBM * ROWB)          // 18432
#define B_ST_B (GBN * ROWB)          // 36864
#define STG_B  (A_ST_B + B_ST_B)     // 55296
#define GEMM_SMEM (NSTAGE * STG_B)   // 165888
#define K_ITERS (IN_DIM / GBK)       // 64

__device__ __forceinline__ uint32_t smem_u32(const void* p) {
    uint32_t a;
    asm("{ .reg .u64 t; cvta.to.shared.u64 t, %1; cvt.u32.u64 %0, t; }" : "=r"(a) : "l"(p));
    return a;
}
#define CP_ASYNC16(dst, src) \
    asm volatile("cp.async.cg.shared.global [%0], [%1], 16;" :: "r"(dst), "l"(src))
#define CP_COMMIT() asm volatile("cp.async.commit_group;" ::: "memory")
#define CP_WAIT1()  asm volatile("cp.async.wait_group 1;" ::: "memory")

#define LDSM_X4(r0, r1, r2, r3, addr) \
    asm volatile("ldmatrix.sync.aligned.m8n8.x4.shared.b16 {%0,%1,%2,%3}, [%4];" \
                 : "=r"(r0), "=r"(r1), "=r"(r2), "=r"(r3) : "r"(addr))

#define MMA16816(d, a, b0, b1) \
    asm volatile("mma.sync.aligned.m16n8k16.row.col.f32.f16.f16.f32 " \
                 "{%0,%1,%2,%3}, {%4,%5,%6,%7}, {%8,%9}, {%0,%1,%2,%3};" \
                 : "+f"((d)[0]), "+f"((d)[1]), "+f"((d)[2]), "+f"((d)[3]) \
                 : "r"((a)[0]), "r"((a)[1]), "r"((a)[2]), "r"((a)[3]), \
                   "r"(b0), "r"(b1))

__device__ __forceinline__ void gemm_load_stage(uint32_t sbase, int stage, int k0,
                                                int m0, int n0, int tid)
{
    uint32_t sb = sbase + stage * STG_B;
    // A: 128 rows x 8 chunks of 16B (128 data bytes per row)
#pragma unroll
    for (int t = 0; t < 4; t++) {
        int i = tid + t * 256;
        int row = i >> 3, c = i & 7;
        const __half* src = g_xh + (size_t)(m0 + row) * IN_DIM + k0 + c * 8;
        CP_ASYNC16(sb + row * ROWB + c * 16, src);
    }
    uint32_t sbB = sb + A_ST_B;
    // B: 256 rows x 8 chunks
#pragma unroll
    for (int t = 0; t < 8; t++) {
        int i = tid + t * 256;
        int row = i >> 3, c = i & 7;
        const __half* src = g_wh + (size_t)(n0 + row) * IN_DIM + k0 + c * 8;
        CP_ASYNC16(sbB + row * ROWB + c * 16, src);
    }
}

__global__ __launch_bounds__(256, 1) void encoder_gemm_hmma(const float* __restrict__ bias)
{
    extern __shared__ __align__(128) char smem[];
    uint32_t sbase = smem_u32(smem);
    const int tid  = threadIdx.x;
    const int lane = tid & 31;
    const int wid  = tid >> 5;
    const int warp_m = wid & 1;
    const int warp_n = wid >> 1;

    // supertile swizzle: 8 m-blocks per group share B columns in L2
    int pid = blockIdx.x;
    int nb = (pid >> 3) & 63;
    int mb = (pid & 7) | ((pid >> 9) << 3);
    int m0 = mb * GBM, n0 = nb * GBN;

    // ldmatrix per-lane addressing
    const int g = lane >> 3;
    const int rA = warp_m * 64 + ((g & 1) << 3) + (lane & 7);
    const int cA = (g >> 1) << 4;                        // bytes
    const int rB = warp_n * 64 + ((g >> 1) << 3) + (lane & 7);
    const int cB = (g & 1) << 4;                         // bytes

    float acc[4][8][4];
#pragma unroll
    for (int i = 0; i < 4; i++)
#pragma unroll
        for (int j = 0; j < 8; j++)
#pragma unroll
            for (int q = 0; q < 4; q++) acc[i][j][q] = 0.0f;

    // prologue: stages 0,1
    gemm_load_stage(sbase, 0, 0, m0, n0, tid); CP_COMMIT();
    gemm_load_stage(sbase, 1, GBK, m0, n0, tid); CP_COMMIT();

    uint32_t af[2][4][4], bf[2][4][4];

    for (int it = 0; it < K_ITERS; it++) {
        int cur = it % 3;
        CP_WAIT1();             // stage `it` resident
        __syncthreads();        // all warps done reading stage (it-1)%3

        // prefetch stage it+2 into the slot just freed ((it+2)%3 == (it-1)%3)
        if (it + 2 < K_ITERS)
            gemm_load_stage(sbase, (it + 2) % 3, (it + 2) * GBK, m0, n0, tid);
        CP_COMMIT();

        uint32_t aST = sbase + cur * STG_B;
        uint32_t bST = aST + A_ST_B;

        // load frags for ks=0 into buffer 0
#pragma unroll
        for (int mf = 0; mf < 4; mf++) {
            uint32_t ad = aST + (uint32_t)((rA + mf * 16) * ROWB + cA);
            LDSM_X4(af[0][mf][0], af[0][mf][1], af[0][mf][2], af[0][mf][3], ad);
        }
#pragma unroll
        for (int nf = 0; nf < 4; nf++) {
            uint32_t bd = bST + (uint32_t)((rB + nf * 16) * ROWB + cB);
            LDSM_X4(bf[0][nf][0], bf[0][nf][1], bf[0][nf][2], bf[0][nf][3], bd);
        }

#pragma unroll
        for (int ks = 0; ks < 4; ks++) {
            int b = ks & 1;
            if (ks < 3) {
                int nb2 = b ^ 1;
                uint32_t koff = (uint32_t)((ks + 1) * 32);
#pragma unroll
                for (int mf = 0; mf < 4; mf++) {
                    uint32_t ad = aST + (uint32_t)((rA + mf * 16) * ROWB + cA) + koff;
                    LDSM_X4(af[nb2][mf][0], af[nb2][mf][1], af[nb2][mf][2], af[nb2][mf][3], ad);
                }
#pragma unroll
                for (int nf = 0; nf < 4; nf++) {
                    uint32_t bd = bST + (uint32_t)((rB + nf * 16) * ROWB + cB) + koff;
                    LDSM_X4(bf[nb2][nf][0], bf[nb2][nf][1], bf[nb2][nf][2], bf[nb2][nf][3], bd);
                }
            }
#pragma unroll
            for (int mf = 0; mf < 4; mf++)
#pragma unroll
                for (int nf = 0; nf < 4; nf++) {
                    MMA16816(acc[mf][nf * 2],     af[b][mf], bf[b][nf][0], bf[b][nf][1]);
                    MMA16816(acc[mf][nf * 2 + 1], af[b][mf], bf[b][nf][2], bf[b][nf][3]);
                }
        }
    }

    // epilogue: bias + relu -> g_features
    int rbase = m0 + warp_m * 64 + (lane >> 2);
    int cbase = n0 + warp_n * 64 + ((lane & 3) << 1);
#pragma unroll
    for (int mf = 0; mf < 4; mf++) {
#pragma unroll
        for (int nf = 0; nf < 8; nf++) {
            int col = cbase + nf * 8;
            float b0 = __ldg(&bias[col]);
            float b1 = __ldg(&bias[col + 1]);
            int r0 = rbase + mf * 16;
            float2 v0, v1;
            v0.x = fmaxf(acc[mf][nf][0] + b0, 0.0f);
            v0.y = fmaxf(acc[mf][nf][1] + b1, 0.0f);
            v1.x = fmaxf(acc[mf][nf][2] + b0, 0.0f);
            v1.y = fmaxf(acc[mf][nf][3] + b1, 0.0f);
            *(float2*)(g_features + (size_t)r0 * HID + col)       = v0;
            *(float2*)(g_features + (size_t)(r0 + 8) * HID + col) = v1;
        }
    }
}

// ============================================================================
// top-k (k=64): radix select on approx + exact boundary refinement
// ============================================================================
#define TOPK_SMEM_BYTES ((HID + 256 + HID / 32) * 4)
#define DELTA 5e-3f
#define ZCAP  64

__device__ __forceinline__ float refine_dot_warp(const float* __restrict__ xr,
                                                 const float* __restrict__ wr,
                                                 float b, int lane)
{
    float s = 0.f, c = 0.f;
    for (int t = 0; t < 16; t++) {
        int base = t * 256 + lane;
        float r = xr[base] * wr[base];
#pragma unroll
        for (int j = 1; j < 8; j++)
            r = fmaf(xr[base + 32 * j], wr[base + 32 * j], r);
        float tt = s + r;
        float z = tt - s;
        float e = (s - (tt - z)) + (r - z);
        c += e; s = tt;
    }
#pragma unroll
    for (int off = 16; off; off >>= 1) {
        float s2 = __shfl_down_sync(0xffffffffu, s, off);
        float c2 = __shfl_down_sync(0xffffffffu, c, off);
        float tt = s + s2;
        float z = tt - s;
        float e = (s - (tt - z)) + (s2 - z);
        c += c2 + e; s = tt;
    }
    float d = s + c;
    return fmaxf(d + b, 0.0f);
}

__global__ __launch_bounds__(256) void topk_kernel(
    float* __restrict__ out_sf,
    const float* __restrict__ x,
    const float* __restrict__ W,
    const float* __restrict__ bias)
{
    extern __shared__ __align__(128) char shraw[];
    uint32_t* sbits = (uint32_t*)shraw;        // HID
    uint32_t* hist  = sbits + HID;             // 256
    uint32_t* keep  = sbits + HID + 256;       // HID/32
    __shared__ uint32_t s_prefix, s_krem;
    __shared__ int s_nhi, s_nzone;
    __shared__ unsigned long long s_sel;
    __shared__ int   s_zidx[ZCAP];
    __shared__ float s_zval[ZCAP];

    int row = blockIdx.x;
    int tid = threadIdx.x;
    int wid = tid >> 5, lane = tid & 31;
    const float* frow = g_features + (size_t)row * HID;

    for (int i = tid; i < HID; i += 256) {
        uint32_t v = __float_as_uint(frow[i]);
        if (v == 0x80000000u) v = 0u;          // -0.0 -> +0.0
        sbits[i] = v;
    }
    if (tid == 0) { s_prefix = 0u; s_krem = KSEL; s_nhi = 0; s_nzone = 0; }
    __syncthreads();

    // radix select: T = 64th largest approx value (as float bits)
    for (int shift = 24; shift >= 0; shift -= 8) {
        hist[tid] = 0;
        __syncthreads();
        uint32_t pmask = (shift == 24) ? 0u : (0xFFFFFFFFu << (shift + 8));
        uint32_t pref  = s_prefix;
        for (int i = tid; i < HID; i += 256) {
            uint32_t v = sbits[i];
            if ((v & pmask) == pref)
                atomicAdd(&hist[(v >> shift) & 0xFFu], 1u);
        }
        __syncthreads();
        if (tid == 0) {
            uint32_t krem = s_krem, cum = 0;
            int d = 255;
            for (; d > 0; d--) {
                if (cum + hist[d] >= krem) break;
                cum += hist[d];
            }
            s_prefix = pref | ((uint32_t)d << shift);
            s_krem   = krem - cum;
        }
        __syncthreads();
    }

    float Tval = __uint_as_float(s_prefix);
    uint32_t Thi = __float_as_uint(Tval + DELTA);
    uint32_t Tlo = __float_as_uint(fmaxf(Tval - DELTA, 0.0f));
    uint32_t T   = s_prefix;

    // classify
    for (int i = tid; i < HID; i += 256) {
        uint32_t v = sbits[i];
        if (v > Thi) atomicAdd(&s_nhi, 1);
        else if (v >= Tlo) {
            int p = atomicAdd(&s_nzone, 1);
            if (p < ZCAP) s_zidx[p] = i;
        }
    }
    __syncthreads();

    int nhi = s_nhi;
    int nzr = s_nzone;
    bool ovf = (nzr > ZCAP);
    int nz = ovf ? ZCAP : nzr;
    int need = KSEL - nhi;

    // exact dots for zone elements (only when ranking matters)
    if (!ovf && nz != need) {
        const float* xr = x + (size_t)row * IN_DIM;
        for (int j = wid; j < nz; j += 8) {
            int h = s_zidx[j];
            float v = refine_dot_warp(xr, W + (size_t)h * IN_DIM, __ldg(&bias[h]), lane);
            if (lane == 0) s_zval[j] = v;
        }
    }
    __syncthreads();

    if (tid == 0) {
        if (ovf) {
            s_sel = 0ull;
        } else if (nz == need) {
            s_sel = (nz >= 64) ? ~0ull : ((1ull << nz) - 1ull);
        } else {
            unsigned long long sel = 0ull;
            for (int pick = 0; pick < need; pick++) {
                int best = -1;
                for (int j = 0; j < nz; j++) {
                    if ((sel >> j) & 1ull) continue;
                    if (best < 0 || s_zval[j] > s_zval[best] ||
                        (s_zval[j] == s_zval[best] && s_zidx[j] < s_zidx[best]))
                        best = j;
                }
                sel |= (1ull << best);
            }
            s_sel = sel;
        }
    }
    __syncthreads();
    unsigned long long sel = s_sel;

    // overwrite selected zone values with exact refined values
    if (!ovf && nz != need && tid < nz) {
        if ((sel >> tid) & 1ull)
            sbits[s_zidx[tid]] = __float_as_uint(s_zval[tid]);
    }
    __syncthreads();

    // keep bitmap
    for (int w = tid; w < HID / 32; w += 256) {
        uint32_t m = 0;
#pragma unroll
        for (int b = 0; b < 32; b++) {
            int i = w * 32 + b;
            uint32_t v = sbits[i];
            bool kp;
            if (ovf) {
                kp = (v >= T);
            } else if (v > Thi) {
                kp = true;
            } else if (v >= Tlo) {
                int slot = -1;
                for (int j = 0; j < nz; j++)
                    if (s_zidx[j] == i) { slot = j; break; }
                kp = (slot >= 0) && ((sel >> slot) & 1ull);
            } else kp = false;
            if (kp) m |= (1u << b);
        }
        keep[w] = m;
    }
    __syncthreads();

    // sparse output row (initializes every element)
    float* orow = out_sf + (size_t)row * HID;
    for (int i = tid; i < HID; i += 256) {
        bool kp = (keep[i >> 5] >> (i & 31)) & 1u;
        orow[i] = kp ? __uint_as_float(sbits[i]) : 0.0f;
    }

    // deterministic compaction (warp 0, index order)
    if (tid < 32) {
        int cnt = 0;
        for (int base = 0; base < HID; base += 32) {
            uint32_t m = keep[base >> 5];
            bool kp = (m >> lane) & 1u;
            int r = __popc(m & ((1u << lane) - 1u));
            if (kp && cnt + r < KSEL) {
                g_vals[row * KSEL + cnt + r] = __uint_as_float(sbits[base + lane]);
                g_idx [row * KSEL + cnt + r] = base + lane;
            }
            cnt += __popc(m);
        }
    }
}

// ============================================================================
// sparse decode  recon[b,:] = sum_j v_j * W_dec^T[h_j, :]
// ============================================================================
__global__ __launch_bounds__(256) void decoder_kernel(float* __restrict__ out_rec)
{
    int row = blockIdx.x;
    int tid = threadIdx.x;
    __shared__ float sv[KSEL];
    __shared__ int   si[KSEL];
    if (tid < KSEL) { sv[tid] = g_vals[row * KSEL + tid]; si[tid] = g_idx[row * KSEL + tid]; }
    __syncthreads();

    float4 acc[4];
#pragma unroll
    for (int w = 0; w < 4; w++) acc[w] = make_float4(0.f, 0.f, 0.f, 0.f);

    for (int j = 0; j < KSEL; j++) {
        float v = sv[j];
        const float4* wp = (const float4*)(g_wdecT + (size_t)si[j] * IN_DIM);
#pragma unroll
        for (int w = 0; w < 4; w++) {
            float4 t = wp[tid + w * 256];
            acc[w].x = fmaf(v, t.x, acc[w].x);
            acc[w].y = fmaf(v, t.y, acc[w].y);
            acc[w].z = fmaf(v, t.z, acc[w].z);
            acc[w].w = fmaf(v, t.w, acc[w].w);
        }
    }
    float4* op = (float4*)(out_rec + (size_t)row * IN_DIM);
#pragma unroll
    for (int w = 0; w < 4; w++) op[tid + w * 256] = acc[w];
}

// ============================================================================
// launch
// ============================================================================
extern "C" void kernel_launch(void* const* d_in, const int* in_sizes, int n_in,
                              void* d_out, int out_size)
{
    const float* x     = (const float*)d_in[0];
    const float* W_enc = (const float*)d_in[1];
    const float* b_enc = (const float*)d_in[2];
    const float* W_dec = (const float*)d_in[3];

    float* out_sf  = (float*)d_out;
    float* out_rec = out_sf + (size_t)BATCH * HID;

    __half *xh, *wh;
    cudaGetSymbolAddress((void**)&xh, g_xh);
    cudaGetSymbolAddress((void**)&wh, g_wh);

    // 1) fp16 conversions
    size_t nx4 = (size_t)BATCH * IN_DIM / 4;
    size_t nw4 = (size_t)HID * IN_DIM / 4;
    to_half_kernel<<<(unsigned)(nx4 / 256), 256>>>(x, xh, nx4);
    to_half_kernel<<<(unsigned)(nw4 / 256), 256>>>(W_enc, wh, nw4);

    // 2) transpose W_dec
    wdec_transpose<<<dim3(HID / 32, IN_DIM / 32), dim3(32, 8)>>>(W_dec);

    // 3) approx encoder GEMM (HMMA fp16, fp32 accum)
    cudaFuncSetAttribute(encoder_gemm_hmma, cudaFuncAttributeMaxDynamicSharedMemorySize,
                         GEMM_SMEM);
    encoder_gemm_hmma<<<(HID / GBN) * (BATCH / GBM), 256, GEMM_SMEM>>>(b_enc);

    // 4) top-k with exact boundary refinement
    cudaFuncSetAttribute(topk_kernel, cudaFuncAttributeMaxDynamicSharedMemorySize,
                         TOPK_SMEM_BYTES);
    topk_kernel<<<BATCH, 256, TOPK_SMEM_BYTES>>>(out_sf, x, W_enc, b_enc);

    // 5) sparse decode
    decoder_kernel<<<BATCH, 256>>>(out_rec);
}

// round 7
// speedup vs baseline: 10.0134x; 1.0594x over previous
#include <cuda_runtime.h>
#include <cuda_fp16.h>
#include <cstdint>
#include <cstddef>

#define BATCH   8192
#define IN_DIM  4096
#define HID     16384
#define KSEL    64

// -------- scratch (allocation-free: __device__ globals) --------
__device__ __half g_wdecT[(size_t)HID * IN_DIM];     // W_dec^T in fp16 [HID, IN_DIM]
__device__ float  g_vals[BATCH * KSEL];
__device__ int    g_idx [BATCH * KSEL];
__device__ __half g_xh[(size_t)BATCH * IN_DIM];      // fp16(x)
__device__ __half g_wh[(size_t)HID * IN_DIM];        // fp16(W_enc)

// ============================================================================
// fp32 -> fp16 conversion
// ============================================================================
__global__ __launch_bounds__(256) void to_half_kernel(
    const float* __restrict__ src, __half* __restrict__ dst, size_t n4)
{
    size_t i = (size_t)blockIdx.x * 256 + threadIdx.x;
    if (i >= n4) return;
    float4 v = ((const float4*)src)[i];
    __half2* d = (__half2*)dst;
    d[2 * i]     = __floats2half2_rn(v.x, v.y);
    d[2 * i + 1] = __floats2half2_rn(v.z, v.w);
}

// ============================================================================
// transpose W_dec [IN_DIM, HID] -> g_wdecT (fp16) [HID, IN_DIM]
// ============================================================================
__global__ void wdec_transpose(const float* __restrict__ W)
{
    __shared__ float tile[32][33];
    int h0 = blockIdx.x * 32;
    int d0 = blockIdx.y * 32;
    int tx = threadIdx.x, ty = threadIdx.y;
#pragma unroll
    for (int r = 0; r < 32; r += 8)
        tile[ty + r][tx] = W[(size_t)(d0 + ty + r) * HID + (h0 + tx)];
    __syncthreads();
#pragma unroll
    for (int r = 0; r < 32; r += 8)
        g_wdecT[(size_t)(h0 + ty + r) * IN_DIM + (d0 + tx)] =
            __float2half_rn(tile[tx][ty + r]);
}

// ============================================================================
// Encoder GEMM: fp16 mma.sync (HMMA), fp32 accumulate
//   BM=128, BN=256, BK=64, 16 warps (2x8), warp tile 64x32, 3-stage cp.async
//   Writes features directly into out_sf (d_out).
// ============================================================================
#define GBM 128
#define GBN 256
#define GBK 64
#define NSTAGE 3
#define ROWB 144                     // 64 fp16 (128B) + 16B pad; conflict-free
#define A_ST_B (GBM * ROWB)          // 18432
#define B_ST_B (GBN * ROWB)          // 36864
#define STG_B  (A_ST_B + B_ST_B)     // 55296
#define GEMM_SMEM (NSTAGE * STG_B)   // 165888
#define K_ITERS (IN_DIM / GBK)       // 64
#define GEMM_THREADS 512

__device__ __forceinline__ uint32_t smem_u32(const void* p) {
    uint32_t a;
    asm("{ .reg .u64 t; cvta.to.shared.u64 t, %1; cvt.u32.u64 %0, t; }" : "=r"(a) : "l"(p));
    return a;
}
#define CP_ASYNC16(dst, src) \
    asm volatile("cp.async.cg.shared.global [%0], [%1], 16;" :: "r"(dst), "l"(src))
#define CP_COMMIT() asm volatile("cp.async.commit_group;" ::: "memory")
#define CP_WAIT1()  asm volatile("cp.async.wait_group 1;" ::: "memory")

#define LDSM_X4(r0, r1, r2, r3, addr) \
    asm volatile("ldmatrix.sync.aligned.m8n8.x4.shared.b16 {%0,%1,%2,%3}, [%4];" \
                 : "=r"(r0), "=r"(r1), "=r"(r2), "=r"(r3) : "r"(addr))

#define MMA16816(d, a, b0, b1) \
    asm volatile("mma.sync.aligned.m16n8k16.row.col.f32.f16.f16.f32 " \
                 "{%0,%1,%2,%3}, {%4,%5,%6,%7}, {%8,%9}, {%0,%1,%2,%3};" \
                 : "+f"((d)[0]), "+f"((d)[1]), "+f"((d)[2]), "+f"((d)[3]) \
                 : "r"((a)[0]), "r"((a)[1]), "r"((a)[2]), "r"((a)[3]), \
                   "r"(b0), "r"(b1))

__device__ __forceinline__ void gemm_load_stage(uint32_t sbase, int stage, int k0,
                                                int m0, int n0, int tid)
{
    uint32_t sb = sbase + stage * STG_B;
    // A: 128 rows x 8 chunks of 16B
#pragma unroll
    for (int t = 0; t < 2; t++) {
        int i = tid + t * GEMM_THREADS;
        int row = i >> 3, c = i & 7;
        const __half* src = g_xh + (size_t)(m0 + row) * IN_DIM + k0 + c * 8;
        CP_ASYNC16(sb + row * ROWB + c * 16, src);
    }
    uint32_t sbB = sb + A_ST_B;
    // B: 256 rows x 8 chunks
#pragma unroll
    for (int t = 0; t < 4; t++) {
        int i = tid + t * GEMM_THREADS;
        int row = i >> 3, c = i & 7;
        const __half* src = g_wh + (size_t)(n0 + row) * IN_DIM + k0 + c * 8;
        CP_ASYNC16(sbB + row * ROWB + c * 16, src);
    }
}

__global__ __launch_bounds__(GEMM_THREADS, 1) void encoder_gemm_hmma(
    const float* __restrict__ bias, float* __restrict__ out_sf)
{
    extern __shared__ __align__(128) char smem[];
    uint32_t sbase = smem_u32(smem);
    const int tid  = threadIdx.x;
    const int lane = tid & 31;
    const int wid  = tid >> 5;
    const int warp_m = wid & 1;       // 0..1  -> 64-row half
    const int warp_n = wid >> 1;      // 0..7  -> 32-col slice

    // supertile swizzle: 8 m-blocks per group share B columns in L2
    int pid = blockIdx.x;
    int nb = (pid >> 3) & 63;
    int mb = (pid & 7) | ((pid >> 9) << 3);
    int m0 = mb * GBM, n0 = nb * GBN;

    // ldmatrix per-lane addressing
    const int g = lane >> 3;
    const int rA = warp_m * 64 + ((g & 1) << 3) + (lane & 7);
    const int cA = (g >> 1) << 4;                        // bytes
    const int rB = warp_n * 32 + ((g >> 1) << 3) + (lane & 7);
    const int cB = (g & 1) << 4;                         // bytes

    float acc[4][4][4];
#pragma unroll
    for (int i = 0; i < 4; i++)
#pragma unroll
        for (int j = 0; j < 4; j++)
#pragma unroll
            for (int q = 0; q < 4; q++) acc[i][j][q] = 0.0f;

    // prologue: stages 0,1
    gemm_load_stage(sbase, 0, 0, m0, n0, tid); CP_COMMIT();
    gemm_load_stage(sbase, 1, GBK, m0, n0, tid); CP_COMMIT();

    for (int it = 0; it < K_ITERS; it++) {
        int cur = it % 3;
        CP_WAIT1();             // stage `it` resident
        __syncthreads();        // all warps done reading stage (it-1)%3

        // prefetch stage it+2 into the freed slot
        if (it + 2 < K_ITERS)
            gemm_load_stage(sbase, (it + 2) % 3, (it + 2) * GBK, m0, n0, tid);
        CP_COMMIT();

        uint32_t aST = sbase + cur * STG_B;
        uint32_t bST = aST + A_ST_B;

#pragma unroll
        for (int ks = 0; ks < 4; ks++) {
            uint32_t koff = (uint32_t)(ks * 32);
            uint32_t af[4][4], bf[2][4];
#pragma unroll
            for (int mf = 0; mf < 4; mf++) {
                uint32_t ad = aST + (uint32_t)((rA + mf * 16) * ROWB + cA) + koff;
                LDSM_X4(af[mf][0], af[mf][1], af[mf][2], af[mf][3], ad);
            }
#pragma unroll
            for (int nf = 0; nf < 2; nf++) {
                uint32_t bd = bST + (uint32_t)((rB + nf * 16) * ROWB + cB) + koff;
                LDSM_X4(bf[nf][0], bf[nf][1], bf[nf][2], bf[nf][3], bd);
            }
#pragma unroll
            for (int mf = 0; mf < 4; mf++)
#pragma unroll
                for (int nf = 0; nf < 2; nf++) {
                    MMA16816(acc[mf][nf * 2],     af[mf], bf[nf][0], bf[nf][1]);
                    MMA16816(acc[mf][nf * 2 + 1], af[mf], bf[nf][2], bf[nf][3]);
                }
        }
    }

    // epilogue: bias + relu -> out_sf (dense approx features)
    int rbase = m0 + warp_m * 64 + (lane >> 2);
    int cbase = n0 + warp_n * 32 + ((lane & 3) << 1);
#pragma unroll
    for (int mf = 0; mf < 4; mf++) {
#pragma unroll
        for (int nf = 0; nf < 4; nf++) {
            int col = cbase + nf * 8;
            float b0 = __ldg(&bias[col]);
            float b1 = __ldg(&bias[col + 1]);
            int r0 = rbase + mf * 16;
            float2 v0, v1;
            v0.x = fmaxf(acc[mf][nf][0] + b0, 0.0f);
            v0.y = fmaxf(acc[mf][nf][1] + b1, 0.0f);
            v1.x = fmaxf(acc[mf][nf][2] + b0, 0.0f);
            v1.y = fmaxf(acc[mf][nf][3] + b1, 0.0f);
            *(float2*)(out_sf + (size_t)r0 * HID + col)       = v0;
            *(float2*)(out_sf + (size_t)(r0 + 8) * HID + col) = v1;
        }
    }
}

// ============================================================================
// top-k (k=64): radix select on approx + exact boundary refinement
//   Reads/writes out_sf in place: zeroes non-kept positives, overwrites
//   refined kept values. GEMM already wrote all elements.
// ============================================================================
#define TOPK_SMEM_BYTES ((HID + 256 + HID / 32) * 4)
#define DELTA 5e-3f
#define ZCAP  64

__device__ __forceinline__ float refine_dot_warp(const float* __restrict__ xr,
                                                 const float* __restrict__ wr,
                                                 float b, int lane)
{
    float s = 0.f, c = 0.f;
    for (int t = 0; t < 16; t++) {
        int base = t * 256 + lane;
        float r = xr[base] * wr[base];
#pragma unroll
        for (int j = 1; j < 8; j++)
            r = fmaf(xr[base + 32 * j], wr[base + 32 * j], r);
        float tt = s + r;
        float z = tt - s;
        float e = (s - (tt - z)) + (r - z);
        c += e; s = tt;
    }
#pragma unroll
    for (int off = 16; off; off >>= 1) {
        float s2 = __shfl_down_sync(0xffffffffu, s, off);
        float c2 = __shfl_down_sync(0xffffffffu, c, off);
        float tt = s + s2;
        float z = tt - s;
        float e = (s - (tt - z)) + (s2 - z);
        c += c2 + e; s = tt;
    }
    float d = s + c;
    return fmaxf(d + b, 0.0f);
}

__global__ __launch_bounds__(256) void topk_kernel(
    float* __restrict__ out_sf,
    const float* __restrict__ x,
    const float* __restrict__ W,
    const float* __restrict__ bias)
{
    extern __shared__ __align__(128) char shraw[];
    uint32_t* sbits = (uint32_t*)shraw;        // HID
    uint32_t* hist  = sbits + HID;             // 256
    uint32_t* keep  = sbits + HID + 256;       // HID/32
    __shared__ uint32_t s_prefix, s_krem;
    __shared__ int s_nhi, s_nzone;
    __shared__ unsigned long long s_sel;
    __shared__ int   s_zidx[ZCAP];
    __shared__ float s_zval[ZCAP];

    int row = blockIdx.x;
    int tid = threadIdx.x;
    int wid = tid >> 5, lane = tid & 31;
    float* orow = out_sf + (size_t)row * HID;

    for (int i = tid; i < HID; i += 256) {
        uint32_t v = __float_as_uint(orow[i]);
        if (v == 0x80000000u) v = 0u;          // -0.0 -> +0.0 (paranoia)
        sbits[i] = v;
    }
    if (tid == 0) { s_prefix = 0u; s_krem = KSEL; s_nhi = 0; s_nzone = 0; }
    __syncthreads();

    // radix select: T = 64th largest approx value (as float bits)
    for (int shift = 24; shift >= 0; shift -= 8) {
        hist[tid] = 0;
        __syncthreads();
        uint32_t pmask = (shift == 24) ? 0u : (0xFFFFFFFFu << (shift + 8));
        uint32_t pref  = s_prefix;
        for (int i = tid; i < HID; i += 256) {
            uint32_t v = sbits[i];
            if ((v & pmask) == pref)
                atomicAdd(&hist[(v >> shift) & 0xFFu], 1u);
        }
        __syncthreads();
        if (tid == 0) {
            uint32_t krem = s_krem, cum = 0;
            int d = 255;
            for (; d > 0; d--) {
                if (cum + hist[d] >= krem) break;
                cum += hist[d];
            }
            s_prefix = pref | ((uint32_t)d << shift);
            s_krem   = krem - cum;
        }
        __syncthreads();
    }

    float Tval = __uint_as_float(s_prefix);
    uint32_t Thi = __float_as_uint(Tval + DELTA);
    uint32_t Tlo = __float_as_uint(fmaxf(Tval - DELTA, 0.0f));
    uint32_t T   = s_prefix;

    // classify
    for (int i = tid; i < HID; i += 256) {
        uint32_t v = sbits[i];
        if (v > Thi) atomicAdd(&s_nhi, 1);
        else if (v >= Tlo) {
            int p = atomicAdd(&s_nzone, 1);
            if (p < ZCAP) s_zidx[p] = i;
        }
    }
    __syncthreads();

    int nhi = s_nhi;
    int nzr = s_nzone;
    bool ovf = (nzr > ZCAP);
    int nz = ovf ? ZCAP : nzr;
    int need = KSEL - nhi;

    // exact dots for zone elements (only when ranking matters)
    if (!ovf && nz != need) {
        const float* xr = x + (size_t)row * IN_DIM;
        for (int j = wid; j < nz; j += 8) {
            int h = s_zidx[j];
            float v = refine_dot_warp(xr, W + (size_t)h * IN_DIM, __ldg(&bias[h]), lane);
            if (lane == 0) s_zval[j] = v;
        }
    }
    __syncthreads();

    if (tid == 0) {
        if (ovf) {
            s_sel = 0ull;
        } else if (nz == need) {
            s_sel = (nz >= 64) ? ~0ull : ((1ull << nz) - 1ull);
        } else {
            unsigned long long sel = 0ull;
            for (int pick = 0; pick < need; pick++) {
                int best = -1;
                for (int j = 0; j < nz; j++) {
                    if ((sel >> j) & 1ull) continue;
                    if (best < 0 || s_zval[j] > s_zval[best] ||
                        (s_zval[j] == s_zval[best] && s_zidx[j] < s_zidx[best]))
                        best = j;
                }
                sel |= (1ull << best);
            }
            s_sel = sel;
        }
    }
    __syncthreads();
    unsigned long long sel = s_sel;

    // overwrite selected zone values with exact refined values
    if (!ovf && nz != need && tid < nz) {
        if ((sel >> tid) & 1ull)
            sbits[s_zidx[tid]] = __float_as_uint(s_zval[tid]);
    }
    __syncthreads();

    // keep bitmap
    for (int w = tid; w < HID / 32; w += 256) {
        uint32_t m = 0;
#pragma unroll
        for (int b = 0; b < 32; b++) {
            int i = w * 32 + b;
            uint32_t v = sbits[i];
            bool kp;
            if (ovf) {
                kp = (v >= T);
            } else if (v > Thi) {
                kp = true;
            } else if (v >= Tlo) {
                int slot = -1;
                for (int j = 0; j < nz; j++)
                    if (s_zidx[j] == i) { slot = j; break; }
                kp = (slot >= 0) && ((sel >> slot) & 1ull);
            } else kp = false;
            if (kp) m |= (1u << b);
        }
        keep[w] = m;
    }
    __syncthreads();

    // in-place sparsify: write only elements that change
    for (int i = tid; i < HID; i += 256) {
        uint32_t v = sbits[i];
        bool kp = (keep[i >> 5] >> (i & 31)) & 1u;
        if (kp)          orow[i] = __uint_as_float(v);  // includes refined values
        else if (v != 0) orow[i] = 0.0f;                // zero out non-kept positive
    }

    // deterministic compaction (warp 0, index order)
    if (tid < 32) {
        int cnt = 0;
        for (int base = 0; base < HID; base += 32) {
            uint32_t m = keep[base >> 5];
            bool kp = (m >> lane) & 1u;
            int r = __popc(m & ((1u << lane) - 1u));
            if (kp && cnt + r < KSEL) {
                g_vals[row * KSEL + cnt + r] = __uint_as_float(sbits[base + lane]);
                g_idx [row * KSEL + cnt + r] = base + lane;
            }
            cnt += __popc(m);
        }
    }
}

// ============================================================================
// sparse decode  recon[b,:] = sum_j v_j * W_dec^T[h_j, :]  (fp16 weights)
// ============================================================================
__global__ __launch_bounds__(256) void decoder_kernel(float* __restrict__ out_rec)
{
    int row = blockIdx.x;
    int tid = threadIdx.x;
    __shared__ float sv[KSEL];
    __shared__ int   si[KSEL];
    if (tid < KSEL) { sv[tid] = g_vals[row * KSEL + tid]; si[tid] = g_idx[row * KSEL + tid]; }
    __syncthreads();

    float acc[16];
#pragma unroll
    for (int q = 0; q < 16; q++) acc[q] = 0.0f;

    for (int j = 0; j < KSEL; j++) {
        float v = sv[j];
        const uint4* wp = (const uint4*)(g_wdecT + (size_t)si[j] * IN_DIM);
#pragma unroll
        for (int w = 0; w < 2; w++) {
            uint4 t = wp[tid + w * 256];      // 8 halves
            __half2 h0 = *(__half2*)&t.x;
            __half2 h1 = *(__half2*)&t.y;
            __half2 h2 = *(__half2*)&t.z;
            __half2 h3 = *(__half2*)&t.w;
            float2 f0 = __half22float2(h0);
            float2 f1 = __half22float2(h1);
            float2 f2 = __half22float2(h2);
            float2 f3 = __half22float2(h3);
            acc[w*8+0] = fmaf(v, f0.x, acc[w*8+0]);
            acc[w*8+1] = fmaf(v, f0.y, acc[w*8+1]);
            acc[w*8+2] = fmaf(v, f1.x, acc[w*8+2]);
            acc[w*8+3] = fmaf(v, f1.y, acc[w*8+3]);
            acc[w*8+4] = fmaf(v, f2.x, acc[w*8+4]);
            acc[w*8+5] = fmaf(v, f2.y, acc[w*8+5]);
            acc[w*8+6] = fmaf(v, f3.x, acc[w*8+6]);
            acc[w*8+7] = fmaf(v, f3.y, acc[w*8+7]);
        }
    }
    // layout: thread t, chunk w covers cols (t + w*256)*8 .. +7  -> matches loads
    float* op = out_rec + (size_t)row * IN_DIM;
#pragma unroll
    for (int w = 0; w < 2; w++) {
        *(float4*)(op + (tid + w * 256) * 8)     = *(float4*)(&acc[w*8]);
        *(float4*)(op + (tid + w * 256) * 8 + 4) = *(float4*)(&acc[w*8+4]);
    }
}

// ============================================================================
// launch
// ============================================================================
extern "C" void kernel_launch(void* const* d_in, const int* in_sizes, int n_in,
                              void* d_out, int out_size)
{
    const float* x     = (const float*)d_in[0];
    const float* W_enc = (const float*)d_in[1];
    const float* b_enc = (const float*)d_in[2];
    const float* W_dec = (const float*)d_in[3];

    float* out_sf  = (float*)d_out;
    float* out_rec = out_sf + (size_t)BATCH * HID;

    __half *xh, *wh;
    cudaGetSymbolAddress((void**)&xh, g_xh);
    cudaGetSymbolAddress((void**)&wh, g_wh);

    // 1) fp16 conversions
    size_t nx4 = (size_t)BATCH * IN_DIM / 4;
    size_t nw4 = (size_t)HID * IN_DIM / 4;
    to_half_kernel<<<(unsigned)(nx4 / 256), 256>>>(x, xh, nx4);
    to_half_kernel<<<(unsigned)(nw4 / 256), 256>>>(W_enc, wh, nw4);

    // 2) transpose W_dec -> fp16
    wdec_transpose<<<dim3(HID / 32, IN_DIM / 32), dim3(32, 8)>>>(W_dec);

    // 3) approx encoder GEMM (HMMA fp16, fp32 accum) -> out_sf (dense)
    cudaFuncSetAttribute(encoder_gemm_hmma, cudaFuncAttributeMaxDynamicSharedMemorySize,
                         GEMM_SMEM);
    encoder_gemm_hmma<<<(HID / GBN) * (BATCH / GBM), GEMM_THREADS, GEMM_SMEM>>>(b_enc, out_sf);

    // 4) top-k with exact boundary refinement (in-place on out_sf)
    cudaFuncSetAttribute(topk_kernel, cudaFuncAttributeMaxDynamicSharedMemorySize,
                         TOPK_SMEM_BYTES);
    topk_kernel<<<BATCH, 256, TOPK_SMEM_BYTES>>>(out_sf, x, W_enc, b_enc);

    // 5) sparse decode (fp16 weights)
    decoder_kernel<<<BATCH, 256>>>(out_rec);
}